// round 1
// baseline (speedup 1.0000x reference)
#include <cuda_runtime.h>

typedef unsigned long long ull;

#define TLEN 4000
#define HID  64
#define NG   256   // 4*H gate rows
#define BT   2     // batch elements per CTA

__device__ __forceinline__ void ffma2(ull &d, ull a, ull b) {
    asm("fma.rn.f32x2 %0, %1, %2, %0;" : "+l"(d) : "l"(a), "l"(b));
}
__device__ __forceinline__ float2 unpack2(ull v) {
    float2 r;
    asm("mov.b64 {%0, %1}, %2;" : "=f"(r.x), "=f"(r.y) : "l"(v));
    return r;
}
__device__ __forceinline__ ull pack2(float x, float y) {
    ull r;
    asm("mov.b64 %0, {%1, %2};" : "=l"(r) : "f"(x), "f"(y));
    return r;
}
__device__ __forceinline__ float sigmoidf_(float v) {
    return 1.0f / (1.0f + __expf(-v));
}

__global__ void __launch_bounds__(256, 1)
lstm2_fused(const float* __restrict__ x,
            const float* __restrict__ W_ih0,
            const float* __restrict__ W_hh0,
            const float* __restrict__ b_ih0,
            const float* __restrict__ b_hh0,
            const float* __restrict__ W_ih1,
            const float* __restrict__ W_hh1,
            const float* __restrict__ b_ih1,
            const float* __restrict__ b_hh1,
            const float* __restrict__ W_fc,
            const float* __restrict__ b_fc,
            float* __restrict__ out)
{
    __shared__ __align__(16) float sh_x[BT * TLEN];       // 32 KB staged input
    __shared__ __align__(16) float sh_hcat[BT][2 * HID];  // [h0 | h1] per batch
    __shared__ __align__(16) float sh_gA[NG][BT];         // layer0 gates
    __shared__ __align__(16) float sh_gB[NG][BT];         // layer1 gates

    const int tid   = threadIdx.x;
    const int g     = tid;                  // gate row this thread owns
    const int bbase = blockIdx.x * BT;      // global batch base

    // Stage x: the CTA's two batch rows are contiguous in global -> linear copy.
    {
        const float4* xg = (const float4*)(x + (size_t)bbase * TLEN);
        float4* xs = (float4*)sh_x;
        for (int i = tid; i < BT * TLEN / 4; i += NG) xs[i] = xg[i];
    }

    // Per-thread weight rows in registers as packed f32 pairs.
    ull wA[32];   // W_hh0 row g (64 floats)
    ull wB[64];   // [W_ih1 row g | W_hh1 row g] (128 floats)
    {
        const ulonglong2* p = (const ulonglong2*)(W_hh0 + g * HID);
        #pragma unroll
        for (int q = 0; q < 16; q++) { ulonglong2 v = p[q]; wA[2*q] = v.x; wA[2*q+1] = v.y; }
        p = (const ulonglong2*)(W_ih1 + g * HID);
        #pragma unroll
        for (int q = 0; q < 16; q++) { ulonglong2 v = p[q]; wB[2*q] = v.x; wB[2*q+1] = v.y; }
        p = (const ulonglong2*)(W_hh1 + g * HID);
        #pragma unroll
        for (int q = 0; q < 16; q++) { ulonglong2 v = p[q]; wB[32+2*q] = v.x; wB[33+2*q] = v.y; }
    }
    const float wx    = W_ih0[g];
    const float biasA = b_ih0[g] + b_hh0[g];
    const float biasB = b_ih1[g] + b_hh1[g];

    ((float*)sh_hcat)[tid] = 0.0f;   // BT*2*HID == 256 floats, one per thread

    float c0 = 0.0f, c1 = 0.0f;      // cell state (threads 0..127: (batch,pj))
    const int pj = tid & (HID - 1);
    const int pb = (tid >> 6) & 1;

    __syncthreads();

    for (int t = 0; t < TLEN; ++t) {
        // ---- layer0 gates: W_hh0*h0 + x*wx + bias ----
        {
            const float xa = sh_x[t];
            const float xb = sh_x[TLEN + t];
            ull a0  = pack2(fmaf(xa, wx, biasA), 0.0f);
            ull a1  = pack2(fmaf(xb, wx, biasA), 0.0f);
            ull a0b = pack2(0.0f, 0.0f), a1b = pack2(0.0f, 0.0f);
            const ulonglong2* h0 = (const ulonglong2*)&sh_hcat[0][0];
            const ulonglong2* h1 = (const ulonglong2*)&sh_hcat[1][0];
            #pragma unroll
            for (int q = 0; q < 16; q += 2) {
                ulonglong2 v0 = h0[q],   v1 = h1[q];
                ffma2(a0,  wA[2*q],   v0.x); ffma2(a0,  wA[2*q+1], v0.y);
                ffma2(a1,  wA[2*q],   v1.x); ffma2(a1,  wA[2*q+1], v1.y);
                ulonglong2 u0 = h0[q+1], u1 = h1[q+1];
                ffma2(a0b, wA[2*q+2], u0.x); ffma2(a0b, wA[2*q+3], u0.y);
                ffma2(a1b, wA[2*q+2], u1.x); ffma2(a1b, wA[2*q+3], u1.y);
            }
            float2 r0 = unpack2(a0), r0b = unpack2(a0b);
            float2 r1 = unpack2(a1), r1b = unpack2(a1b);
            ((float2*)sh_gA)[g] = make_float2((r0.x + r0.y) + (r0b.x + r0b.y),
                                              (r1.x + r1.y) + (r1b.x + r1b.y));
        }
        __syncthreads();                         // s1
        // ---- layer0 pointwise (threads 0..127 own (batch pb, cell pj)) ----
        if (tid < NG / 2) {
            float gi = sh_gA[pj          ][pb];
            float gf = sh_gA[pj +     HID][pb];
            float gc = sh_gA[pj + 2 * HID][pb];
            float go = sh_gA[pj + 3 * HID][pb];
            float iv = sigmoidf_(gi), fv = sigmoidf_(gf), ov = sigmoidf_(go);
            float cv = tanhf(gc);
            c0 = fv * c0 + iv * cv;
            sh_hcat[pb][pj] = ov * tanhf(c0);    // h0_new
        }
        __syncthreads();                         // s2
        // ---- layer1 gates: [W_ih1|W_hh1]*[h0_new; h1] + bias ----
        {
            ull a0  = pack2(biasB, 0.0f);
            ull a1  = a0;
            ull a0b = pack2(0.0f, 0.0f), a1b = a0b;
            const ulonglong2* h0 = (const ulonglong2*)&sh_hcat[0][0];
            const ulonglong2* h1 = (const ulonglong2*)&sh_hcat[1][0];
            #pragma unroll
            for (int q = 0; q < 32; q += 2) {
                ulonglong2 v0 = h0[q],   v1 = h1[q];
                ffma2(a0,  wB[2*q],   v0.x); ffma2(a0,  wB[2*q+1], v0.y);
                ffma2(a1,  wB[2*q],   v1.x); ffma2(a1,  wB[2*q+1], v1.y);
                ulonglong2 u0 = h0[q+1], u1 = h1[q+1];
                ffma2(a0b, wB[2*q+2], u0.x); ffma2(a0b, wB[2*q+3], u0.y);
                ffma2(a1b, wB[2*q+2], u1.x); ffma2(a1b, wB[2*q+3], u1.y);
            }
            float2 r0 = unpack2(a0), r0b = unpack2(a0b);
            float2 r1 = unpack2(a1), r1b = unpack2(a1b);
            ((float2*)sh_gB)[g] = make_float2((r0.x + r0.y) + (r0b.x + r0b.y),
                                              (r1.x + r1.y) + (r1b.x + r1b.y));
        }
        __syncthreads();                         // s3
        // ---- layer1 pointwise; overlaps with next step's phase A (no s4:
        // phase A only touches sh_hcat[:,0:64] and sh_gA; s1 of the next
        // iteration orders these h1 writes before phase B reads them). ----
        if (tid < NG / 2) {
            float gi = sh_gB[pj          ][pb];
            float gf = sh_gB[pj +     HID][pb];
            float gc = sh_gB[pj + 2 * HID][pb];
            float go = sh_gB[pj + 3 * HID][pb];
            float iv = sigmoidf_(gi), fv = sigmoidf_(gf), ov = sigmoidf_(go);
            float cv = tanhf(gc);
            c1 = fv * c1 + iv * cv;
            sh_hcat[pb][HID + pj] = ov * tanhf(c1);  // h1_new
        }
    }
    __syncthreads();

    // ---- FC head on final h1: out[b][e] = W_fc[e,:]·h1_b + b_fc[e] ----
    {
        const int e  = tid >> 1;     // 0..127
        const int bb = tid & 1;      // 0..1
        float acc = b_fc[e];
        const float* wr = W_fc + e * HID;
        const float* hv = &sh_hcat[bb][HID];
        #pragma unroll
        for (int j = 0; j < HID; j += 4) {
            acc = fmaf(wr[j],     hv[j],     acc);
            acc = fmaf(wr[j + 1], hv[j + 1], acc);
            acc = fmaf(wr[j + 2], hv[j + 2], acc);
            acc = fmaf(wr[j + 3], hv[j + 3], acc);
        }
        out[(size_t)(bbase + bb) * 128 + e] = acc;
    }
}

extern "C" void kernel_launch(void* const* d_in, const int* in_sizes, int n_in,
                              void* d_out, int out_size) {
    (void)in_sizes; (void)n_in; (void)out_size;
    lstm2_fused<<<128, 256>>>(
        (const float*)d_in[0],   // x
        (const float*)d_in[1],   // W_ih0
        (const float*)d_in[2],   // W_hh0
        (const float*)d_in[3],   // b_ih0
        (const float*)d_in[4],   // b_hh0
        (const float*)d_in[5],   // W_ih1
        (const float*)d_in[6],   // W_hh1
        (const float*)d_in[7],   // b_ih1
        (const float*)d_in[8],   // b_hh1
        (const float*)d_in[9],   // W_fc
        (const float*)d_in[10],  // b_fc
        (float*)d_out);
}

// round 2
// speedup vs baseline: 1.6895x; 1.6895x over previous
#include <cuda_runtime.h>

typedef unsigned long long ull;

#define TLEN 4000
#define HID  64
#define NG   256   // 4*H gate rows
#define BT   2     // batch elements per CTA

__device__ __forceinline__ void ffma2(ull &d, ull a, ull b) {
    asm("fma.rn.f32x2 %0, %1, %2, %0;" : "+l"(d) : "l"(a), "l"(b));
}
__device__ __forceinline__ float2 unpack2(ull v) {
    float2 r;
    asm("mov.b64 {%0, %1}, %2;" : "=f"(r.x), "=f"(r.y) : "l"(v));
    return r;
}
__device__ __forceinline__ ull pack2(float x, float y) {
    ull r;
    asm("mov.b64 %0, {%1, %2};" : "=l"(r) : "f"(x), "f"(y));
    return r;
}
__device__ __forceinline__ float fsigmoid(float v) {
    // 1/(1+e^-v): MUFU.EX2 + MUFU.RCP, saturates correctly at both ends
    return __fdividef(1.0f, 1.0f + __expf(-v));
}
__device__ __forceinline__ float ftanh(float v) {
    // tanh(v) = 1 - 2/(e^{2v}+1); e^{2v}->inf gives 1, ->0 gives -1
    float e = __expf(2.0f * v);
    return 1.0f - __fdividef(2.0f, e + 1.0f);
}

__global__ void __launch_bounds__(256, 1)
lstm2_fused(const float* __restrict__ x,
            const float* __restrict__ W_ih0,
            const float* __restrict__ W_hh0,
            const float* __restrict__ b_ih0,
            const float* __restrict__ b_hh0,
            const float* __restrict__ W_ih1,
            const float* __restrict__ W_hh1,
            const float* __restrict__ b_ih1,
            const float* __restrict__ b_hh1,
            const float* __restrict__ W_fc,
            const float* __restrict__ b_fc,
            float* __restrict__ out)
{
    __shared__ __align__(16) float sh_x[BT * TLEN];        // 32 KB staged input
    __shared__ __align__(16) float sh_h[BT][2 * HID];      // [h0 | h1] per batch
    __shared__ __align__(16) float sh_g[2][BT][NG];        // gates [layer][batch][row]

    const int tid   = threadIdx.x;
    const int g     = tid;                  // gate row this thread owns (matvec)
    const int bbase = blockIdx.x * BT;

    // Stage x (two contiguous batch rows -> linear copy)
    {
        const float4* xg = (const float4*)(x + (size_t)bbase * TLEN);
        float4* xs = (float4*)sh_x;
        for (int i = tid; i < BT * TLEN / 4; i += NG) xs[i] = xg[i];
    }

    // Per-thread weight rows in registers as packed f32 pairs.
    ull wA[32];   // W_hh0 row g (64 floats)
    ull wB[64];   // [W_ih1 row g | W_hh1 row g] (128 floats)
    {
        const ulonglong2* p = (const ulonglong2*)(W_hh0 + g * HID);
        #pragma unroll
        for (int q = 0; q < 16; q++) { ulonglong2 v = p[q]; wA[2*q] = v.x; wA[2*q+1] = v.y; }
        p = (const ulonglong2*)(W_ih1 + g * HID);
        #pragma unroll
        for (int q = 0; q < 16; q++) { ulonglong2 v = p[q]; wB[2*q] = v.x; wB[2*q+1] = v.y; }
        p = (const ulonglong2*)(W_hh1 + g * HID);
        #pragma unroll
        for (int q = 0; q < 16; q++) { ulonglong2 v = p[q]; wB[32+2*q] = v.x; wB[33+2*q] = v.y; }
    }
    const float wx    = W_ih0[g];
    const float biasA = b_ih0[g] + b_hh0[g];
    const float biasB = b_ih1[g] + b_hh1[g];

    ((float*)sh_h)[tid] = 0.0f;  // zero h0 and h1 (BT*2*HID == 256 floats)

    // Pointwise ownership: thread p -> (layer L, batch pb, unit pj). 256 items.
    const int L  = tid >> 7;
    const int pb = (tid >> 6) & 1;
    const int pj = tid & (HID - 1);
    const float* gp = &sh_g[L][pb][0];
    float c = 0.0f;

    __syncthreads();

    // Software-pipelined: iter k computes gA(k) [layer0, step k] and
    // gB(k-1) [layer1, step k-1] in ONE matvec phase, then ONE pointwise
    // phase produces h0(k) and h1(k-1). 2 barriers per step.
    for (int k = 0; k <= TLEN; ++k) {
        // ---- fused matvec ----
        {
            const int xk = (k < TLEN) ? k : TLEN - 1;   // k==TLEN result discarded
            const float xa = sh_x[xk];
            const float xb = sh_x[TLEN + xk];
            ull aA00 = pack2(fmaf(xa, wx, biasA), 0.0f);
            ull aA10 = pack2(fmaf(xb, wx, biasA), 0.0f);
            ull aA01 = pack2(0.0f, 0.0f), aA11 = aA01;
            ull aB00 = pack2(biasB, 0.0f), aB10 = aB00;
            ull aB01 = pack2(0.0f, 0.0f), aB11 = aB01;

            const ulonglong2* h0b0 = (const ulonglong2*)&sh_h[0][0];
            const ulonglong2* h0b1 = (const ulonglong2*)&sh_h[1][0];
            const ulonglong2* h1b0 = (const ulonglong2*)&sh_h[0][HID];
            const ulonglong2* h1b1 = (const ulonglong2*)&sh_h[1][HID];

            // h0 chunks feed BOTH layer0 (wA) and layer1-ih (wB[0:32]) FMAs
            #pragma unroll
            for (int q = 0; q < 16; q++) {
                ulonglong2 v0 = h0b0[q], v1 = h0b1[q];
                ffma2(aA00, wA[2*q],   v0.x); ffma2(aA01, wA[2*q+1], v0.y);
                ffma2(aA10, wA[2*q],   v1.x); ffma2(aA11, wA[2*q+1], v1.y);
                ffma2(aB00, wB[2*q],   v0.x); ffma2(aB01, wB[2*q+1], v0.y);
                ffma2(aB10, wB[2*q],   v1.x); ffma2(aB11, wB[2*q+1], v1.y);
            }
            // h1 chunks feed layer1-hh (wB[32:64])
            #pragma unroll
            for (int q = 0; q < 16; q++) {
                ulonglong2 u0 = h1b0[q], u1 = h1b1[q];
                ffma2(aB00, wB[32+2*q], u0.x); ffma2(aB01, wB[33+2*q], u0.y);
                ffma2(aB10, wB[32+2*q], u1.x); ffma2(aB11, wB[33+2*q], u1.y);
            }

            float2 r0 = unpack2(aA00), r1 = unpack2(aA01);
            float2 r2 = unpack2(aA10), r3 = unpack2(aA11);
            sh_g[0][0][g] = (r0.x + r0.y) + (r1.x + r1.y);
            sh_g[0][1][g] = (r2.x + r2.y) + (r3.x + r3.y);
            float2 s0 = unpack2(aB00), s1 = unpack2(aB01);
            float2 s2 = unpack2(aB10), s3 = unpack2(aB11);
            sh_g[1][0][g] = (s0.x + s0.y) + (s1.x + s1.y);
            sh_g[1][1][g] = (s2.x + s2.y) + (s3.x + s3.y);
        }
        __syncthreads();
        // ---- pointwise: all 256 threads, one (layer,batch,unit) each ----
        {
            const bool active = L ? (k > 0) : (k < TLEN);
            if (active) {
                float gi = gp[pj          ];
                float gf = gp[pj +     HID];
                float gc = gp[pj + 2 * HID];
                float go = gp[pj + 3 * HID];
                float iv = fsigmoid(gi), fv = fsigmoid(gf), ov = fsigmoid(go);
                float cv = ftanh(gc);
                c = fv * c + iv * cv;
                sh_h[pb][L * HID + pj] = ov * ftanh(c);
            }
        }
        __syncthreads();
    }

    // ---- FC head on final h1 ----
    {
        const int e  = tid >> 1;     // 0..127
        const int bb = tid & 1;      // 0..1
        float acc = b_fc[e];
        const float* wr = W_fc + e * HID;
        const float* hv = &sh_h[bb][HID];
        #pragma unroll
        for (int j = 0; j < HID; j += 4) {
            acc = fmaf(wr[j],     hv[j],     acc);
            acc = fmaf(wr[j + 1], hv[j + 1], acc);
            acc = fmaf(wr[j + 2], hv[j + 2], acc);
            acc = fmaf(wr[j + 3], hv[j + 3], acc);
        }
        out[(size_t)(bbase + bb) * 128 + e] = acc;
    }
}

extern "C" void kernel_launch(void* const* d_in, const int* in_sizes, int n_in,
                              void* d_out, int out_size) {
    (void)in_sizes; (void)n_in; (void)out_size;
    lstm2_fused<<<128, 256>>>(
        (const float*)d_in[0],   // x
        (const float*)d_in[1],   // W_ih0
        (const float*)d_in[2],   // W_hh0
        (const float*)d_in[3],   // b_ih0
        (const float*)d_in[4],   // b_hh0
        (const float*)d_in[5],   // W_ih1
        (const float*)d_in[6],   // W_hh1
        (const float*)d_in[7],   // b_ih1
        (const float*)d_in[8],   // b_hh1
        (const float*)d_in[9],   // W_fc
        (const float*)d_in[10],  // b_fc
        (float*)d_out);
}